// round 8
// baseline (speedup 1.0000x reference)
#include <cuda_runtime.h>
#include <cuda_fp16.h>
#include <cstddef>

// DynMoleRouterLoss fused, round 8: fully-packed f16x2 pipeline.
// Thread processes rows (lp*BS + t) and ((lp+16)*BS + t)  [same token => same attn w].
// Sort, exp (ex2.f16x2), prefix, normalize, top-p compare, P/A accumulation all
// packed half2{rowA,rowB}. Only entropy H is unpacked to fp32 per row.

namespace {
constexpr int   L_     = 32;
constexpr int   BS_    = 8 * 4096;          // 32768 tokens
constexpr int   E_     = 16;
constexpr int   TPB    = 256;
constexpr int   NB     = 296;               // 2 blocks/SM, one wave
constexpr int   WPB    = TPB / 32;
constexpr int   NW     = NB * WPB;          // 2368 warps
constexpr int   UNITSP = 16384;             // pair-units: (L/2) * BS / 32
constexpr int   ROWOFF = 16 * BS_;          // row distance between pair members
constexpr float EPSF_  = 1e-5f;
constexpr float BCT_   = 2.0f;
constexpr float LN2_   = 0.6931471805599453f;
constexpr float DYN_   = 0.001f;
constexpr float AUX_   = 0.001f;
constexpr float NROWSF = 1048576.0f;        // L*BS
}

// [0..15]=A counts, [16..31]=P sums, [32]=entropy, [33]=sum w (pair-units)
__device__ float    g_acc[34];
__device__ unsigned g_ctr = 0;

__device__ __forceinline__ float lg2f(float x) {
    float y; asm("lg2.approx.ftz.f32 %0, %1;" : "=f"(y) : "f"(x)); return y;
}
__device__ __forceinline__ float rcpf(float x) {
    float y; asm("rcp.approx.ftz.f32 %0, %1;" : "=f"(y) : "f"(x)); return y;
}

// packed compare-exchange, DESCENDING per half: h[i] >= h[j] elementwise after
#define CE(i, j) { __half2 _a = h[i], _b = h[j]; h[i] = __hmax2(_a, _b); h[j] = __hmin2(_a, _b); }

__global__ __launch_bounds__(TPB, 2) void dynmole_fused(
        const float* __restrict__ logits, const int* __restrict__ attn,
        float* __restrict__ out) {
    const int lane = threadIdx.x & 31;
    const int warp = threadIdx.x >> 5;
    const int wg   = blockIdx.x * WPB + warp;

    const __half2 L2E2  = __float2half2_rn(1.4426950408889634f);
    const __half2 ZERO2 = __float2half2_rn(0.0f);
    const __half2 ONE2  = __float2half2_rn(1.0f);

    __half2 P2[16], A2h[16];
#pragma unroll
    for (int r = 0; r < 16; r++) { P2[r] = ZERO2; A2h[r] = ZERO2; }
    float entS = 0.0f, wS = 0.0f;

    // ---------------- software-pipelined main loop ----------------
    int pu = wg;
    float4 a0, a1, a2, a3, b0, b1, b2, b3;
    int    w = 0;
    if (pu < UNITSP) {
        const int rowA = pu * 32 + lane;
        const float4* pa = reinterpret_cast<const float4*>(logits) + ((size_t)rowA << 2);
        const float4* pb_ = pa + ((size_t)ROWOFF << 2);
        a0 = __ldg(pa + 0); a1 = __ldg(pa + 1); a2 = __ldg(pa + 2); a3 = __ldg(pa + 3);
        b0 = __ldg(pb_ + 0); b1 = __ldg(pb_ + 1); b2 = __ldg(pb_ + 2); b3 = __ldg(pb_ + 3);
        w  = __ldg(attn + (rowA & (BS_ - 1)));
    }

    while (pu < UNITSP) {
        // pack keys: half2{rowA (low), rowB (high)}
        __half2 h[16];
        h[ 0]=__floats2half2_rn(a0.x,b0.x); h[ 1]=__floats2half2_rn(a0.y,b0.y);
        h[ 2]=__floats2half2_rn(a0.z,b0.z); h[ 3]=__floats2half2_rn(a0.w,b0.w);
        h[ 4]=__floats2half2_rn(a1.x,b1.x); h[ 5]=__floats2half2_rn(a1.y,b1.y);
        h[ 6]=__floats2half2_rn(a1.z,b1.z); h[ 7]=__floats2half2_rn(a1.w,b1.w);
        h[ 8]=__floats2half2_rn(a2.x,b2.x); h[ 9]=__floats2half2_rn(a2.y,b2.y);
        h[10]=__floats2half2_rn(a2.z,b2.z); h[11]=__floats2half2_rn(a2.w,b2.w);
        h[12]=__floats2half2_rn(a3.x,b3.x); h[13]=__floats2half2_rn(a3.y,b3.y);
        h[14]=__floats2half2_rn(a3.z,b3.z); h[15]=__floats2half2_rn(a3.w,b3.w);
        const int curw = w;

        const int un = pu + NW;
        if (un < UNITSP) {     // prefetch next pair (8x LDG.128 + attn)
            const int rowA = un * 32 + lane;
            const float4* pa = reinterpret_cast<const float4*>(logits) + ((size_t)rowA << 2);
            const float4* pb_ = pa + ((size_t)ROWOFF << 2);
            a0 = __ldg(pa + 0); a1 = __ldg(pa + 1); a2 = __ldg(pa + 2); a3 = __ldg(pa + 3);
            b0 = __ldg(pb_ + 0); b1 = __ldg(pb_ + 1); b2 = __ldg(pb_ + 2); b3 = __ldg(pb_ + 3);
            w  = __ldg(attn + (rowA & (BS_ - 1)));
        }
        pu = un;

        // ---- dual Batcher odd-even merge sort, descending (63 packed CEs) ----
        CE(0,1)  CE(2,3)  CE(4,5)  CE(6,7)  CE(8,9)  CE(10,11) CE(12,13) CE(14,15)
        CE(0,2)  CE(1,3)  CE(4,6)  CE(5,7)  CE(8,10) CE(9,11)  CE(12,14) CE(13,15)
        CE(1,2)  CE(5,6)  CE(9,10) CE(13,14)
        CE(0,4)  CE(1,5)  CE(2,6)  CE(3,7)  CE(8,12) CE(9,13)  CE(10,14) CE(11,15)
        CE(2,4)  CE(3,5)  CE(10,12) CE(11,13)
        CE(1,2)  CE(3,4)  CE(5,6)  CE(9,10) CE(11,12) CE(13,14)
        CE(0,8)  CE(1,9)  CE(2,10) CE(3,11) CE(4,12) CE(5,13)  CE(6,14)  CE(7,15)
        CE(4,8)  CE(5,9)  CE(6,10) CE(7,11)
        CE(2,4)  CE(3,5)  CE(6,8)  CE(7,9)  CE(10,12) CE(11,13)
        CE(1,2)  CE(3,4)  CE(5,6)  CE(7,8)  CE(9,10)  CE(11,12) CE(13,14)

        // ---- packed exp + dot + in-place prefix-before (h[r] <- pb2[r]) ----
        const __half2 m2 = h[0];
        __half2 dot2 = ZERO2, cp2 = ZERO2;
#pragma unroll
        for (int r = 0; r < 16; r++) {
            const __half2 d2 = __hsub2(h[r], m2);          // x - m  (<= 0)
            const __half2 ex = h2exp2(__hmul2(d2, L2E2));  // e^(x-m), one MUFU for 2 rows
            dot2 = __hfma2(ex, d2, dot2);                  // sum e*(x-m)
            h[r] = cp2;                                    // prefix BEFORE rank r
            cp2  = __hadd2(cp2, ex);
        }
        const __half2 Z2  = cp2;
        const __half2 rz2 = h2rcp(Z2);
#pragma unroll
        for (int r = 0; r < 16; r++) h[r] = __hmul2(h[r], rz2);   // normalized prefix

        // ---- entropy per row (fp32, unpacked) ----
        const float ZA = __low2float(Z2),  ZB = __high2float(Z2);
        const float dA = __low2float(dot2), dB = __high2float(dot2);
        const float HA = lg2f(ZA) * LN2_ - dA * rcpf(ZA) - 16.0f * EPSF_;
        const float HB = lg2f(ZB) * LN2_ - dB * rcpf(ZB) - 16.0f * EPSF_;
        entS += HA + HB;
        wS   += (float)curw;

        // per-row threshold on NORMALIZED prefix: keep(r) <=> pbn[r] <= thr
        const float thrA = curw ? ((HA >= BCT_) ? 60000.0f : 0.8f) : -1.0f;
        const float thrB = curw ? ((HB >= BCT_) ? 60000.0f : 0.8f) : -1.0f;
        const __half2 thr2 = __floats2half2_rn(thrA, thrB);

        // ---- packed top-p accumulate ----
#pragma unroll
        for (int r = 0; r < 16; r++) {
            const __half2 keep = __hle2(h[r], thr2);               // 1.0 / 0.0 per half
            const __half2 nxt  = (r == 15) ? ONE2 : h[r + 1];
            const __half2 p2   = __hsub2(nxt, h[r]);               // normalized p_r
            P2[r]  = __hfma2(keep, p2, P2[r]);
            A2h[r] = __hadd2(A2h[r], keep);                        // exact (ints <= 7)
        }
    }

    // ---------------- warp butterfly reduction (packed) ----------------
#pragma unroll
    for (int r = 0; r < 16; r++) {
#pragma unroll
        for (int s = 16; s > 0; s >>= 1) {
            P2[r]  = __hadd2(P2[r],  __shfl_xor_sync(0xffffffffu, P2[r],  s));
            A2h[r] = __hadd2(A2h[r], __shfl_xor_sync(0xffffffffu, A2h[r], s));  // <=224, exact
        }
    }
#pragma unroll
    for (int s = 16; s > 0; s >>= 1) {
        entS += __shfl_xor_sync(0xffffffffu, entS, s);
        wS   += __shfl_xor_sync(0xffffffffu, wS,   s);
    }

    // ---------------- block reduce (smem) then RED into g_acc ----------------
    __shared__ float sred[WPB][34];
    if (lane == 0) {
#pragma unroll
        for (int r = 0; r < 16; r++) {
            sred[warp][r]      = __low2float(A2h[r]) + __high2float(A2h[r]);
            sred[warp][16 + r] = __low2float(P2[r])  + __high2float(P2[r]);
        }
        sred[warp][32] = entS;
        sred[warp][33] = wS;
    }
    __syncthreads();
    if (threadIdx.x < 34) {
        float s = 0.0f;
#pragma unroll
        for (int j = 0; j < WPB; j++) s += sred[j][threadIdx.x];
        atomicAdd(&g_acc[threadIdx.x], s);
        __threadfence();
    }
    __syncthreads();

    // ---------------- last block finalizes ----------------
    __shared__ bool  s_last;
    __shared__ float sacc[34];
    if (threadIdx.x == 0) {
        unsigned old = atomicAdd(&g_ctr, 1u);
        s_last = (old == (unsigned)(NB - 1));
    }
    __syncthreads();
    if (!s_last) return;

    __threadfence();
    if (threadIdx.x < 34)
        sacc[threadIdx.x] = atomicAdd(&g_acc[threadIdx.x], 0.0f);
    __syncthreads();
    if (threadIdx.x == 0) {
        const float denom = 2.0f * sacc[33];     // == L * sum(attn)
        const float inv   = 1.0f / denom;
        float overall = 0.0f;
#pragma unroll
        for (int r = 0; r < 16; r++) overall += sacc[r] * sacc[16 + r];
        overall *= inv * inv;
        out[0] = (sacc[32] * (1.0f / NROWSF)) * DYN_ + overall * (float)E_ * AUX_;
        g_ctr = 0;                               // reset for next replay
    }
    if (threadIdx.x < 34) g_acc[threadIdx.x] = 0.0f;
}

extern "C" void kernel_launch(void* const* d_in, const int* in_sizes, int n_in,
                              void* d_out, int out_size) {
    const float* logits;
    const int*   attn;
    if (in_sizes[0] == L_ * BS_ * E_) {
        logits = (const float*)d_in[0];
        attn   = (const int*)d_in[1];
    } else {
        logits = (const float*)d_in[1];
        attn   = (const int*)d_in[0];
    }
    dynmole_fused<<<NB, TPB>>>(logits, attn, (float*)d_out);
}